// round 15
// baseline (speedup 1.0000x reference)
#include <cuda_runtime.h>
#include <cuda_fp16.h>
#include <cstdint>

#define DI __device__ __forceinline__

// ---------------- problem dims ----------------
#define MDIM 8192
#define NDIM 4096
#define KDIM 4096
#define BM 128
#define BN 128
#define BK 64
#define STAGES 3
#define NKT (KDIM / BK)            // 64
#define STAGE_BYTES 32768          // A 16KB + B 16KB
#define B_OFF 16384
#define SMEM_TOTAL (STAGES * STAGE_BYTES)   // 96 KB -> 2 CTAs/SM
#define GRID_GEMM ((MDIM / BM) * (NDIM / BN))  // 2048

// scratch (allocation-free rule: __device__ globals)
__device__ __half g_x16[(size_t)MDIM * KDIM];   // 67 MB
__device__ __half g_w16[(size_t)NDIM * KDIM];   // 33.5 MB

// ---------------- PTX helpers (baseline sm_80+ features only) ----------------
DI uint32_t smem_u32(const void* p) {
    uint32_t a;
    asm("{ .reg .u64 t; cvta.to.shared.u64 t, %1; cvt.u32.u64 %0, t; }" : "=r"(a) : "l"(p));
    return a;
}
DI void cp16(uint32_t dst, const void* src) {
    asm volatile("cp.async.cg.shared.global [%0], [%1], 16;" :: "r"(dst), "l"(src) : "memory");
}
DI void cp_commit() { asm volatile("cp.async.commit_group;" ::: "memory"); }
DI void cp_wait1() { asm volatile("cp.async.wait_group 1;" ::: "memory"); }

DI void ldm_x4(uint32_t* r, uint32_t addr) {
    asm volatile("ldmatrix.sync.aligned.m8n8.x4.shared.b16 {%0,%1,%2,%3}, [%4];"
                 : "=r"(r[0]), "=r"(r[1]), "=r"(r[2]), "=r"(r[3]) : "r"(addr));
}
DI void mma16816(float* c, const uint32_t* a, uint32_t b0, uint32_t b1) {
    asm volatile(
        "mma.sync.aligned.m16n8k16.row.col.f32.f16.f16.f32 "
        "{%0,%1,%2,%3}, {%4,%5,%6,%7}, {%8,%9}, {%0,%1,%2,%3};"
        : "+f"(c[0]), "+f"(c[1]), "+f"(c[2]), "+f"(c[3])
        : "r"(a[0]), "r"(a[1]), "r"(a[2]), "r"(a[3]), "r"(b0), "r"(b1));
}

// ============================================================
// Kernel 1: x fp32 -> fp16 (RNE), 16-byte stores
// ============================================================
__global__ void cvt_kernel(const float* __restrict__ x) {
    size_t i = (size_t)(blockIdx.x * blockDim.x + threadIdx.x) * 2;  // 2 float4 per thread
    float4 v0 = reinterpret_cast<const float4*>(x)[i];
    float4 v1 = reinterpret_cast<const float4*>(x)[i + 1];
    uint4 u;
    __half2 h;
    h = __floats2half2_rn(v0.x, v0.y); u.x = *reinterpret_cast<uint32_t*>(&h);
    h = __floats2half2_rn(v0.z, v0.w); u.y = *reinterpret_cast<uint32_t*>(&h);
    h = __floats2half2_rn(v1.x, v1.y); u.z = *reinterpret_cast<uint32_t*>(&h);
    h = __floats2half2_rn(v1.z, v1.w); u.w = *reinterpret_cast<uint32_t*>(&h);
    reinterpret_cast<uint4*>(g_x16)[i / 2] = u;
}

// ============================================================
// Kernel 2: w16 = fp16(W + 2 * L @ R)   (LORA_SCALE = 32/16 = 2)
// 2048 blocks: (16 o-rows) x (512-col i-chunk); 16-byte stores
// threads: 64 i-groups (8 cols each) x 4 oo-groups (4 rows each)
// ============================================================
__global__ __launch_bounds__(256)
void weff_kernel(const float* __restrict__ W, const float* __restrict__ L,
                 const float* __restrict__ R) {
    __shared__ float Rs[16][512];
    __shared__ float Ls[16][16];
    int o0 = (blockIdx.x >> 3) * 16;          // 256 o-groups
    int i0 = (blockIdx.x & 7) * 512;          // 8 i-chunks
    int tid = threadIdx.x;
    {
        int oo = tid >> 4, k = tid & 15;
        Ls[oo][k] = 2.0f * L[(o0 + oo) * 16 + k];
    }
#pragma unroll
    for (int j = 0; j < 8; j++) {
        int idx = tid + j * 256;              // float4 index into 16x512 tile
        int k = idx >> 7;
        int ii = (idx & 127) << 2;
        *reinterpret_cast<float4*>(&Rs[k][ii]) =
            *reinterpret_cast<const float4*>(&R[(size_t)k * 4096 + i0 + ii]);
    }
    __syncthreads();
    int ii = (tid & 63) * 8;                  // 8 consecutive i per thread
    int og = (tid >> 6) * 4;                  // 4 rows per thread
#pragma unroll
    for (int oo4 = 0; oo4 < 4; oo4++) {
        int o = o0 + og + oo4;
        const float* wp = &W[(size_t)o * 4096 + i0 + ii];
        float4 w0 = *reinterpret_cast<const float4*>(wp);
        float4 w1 = *reinterpret_cast<const float4*>(wp + 4);
        float a0 = w0.x, a1 = w0.y, a2 = w0.z, a3 = w0.w;
        float a4 = w1.x, a5 = w1.y, a6 = w1.z, a7 = w1.w;
#pragma unroll
        for (int k = 0; k < 16; k++) {
            float lk = Ls[og + oo4][k];
            const float* rp = &Rs[k][ii];
            a0 = fmaf(lk, rp[0], a0);
            a1 = fmaf(lk, rp[1], a1);
            a2 = fmaf(lk, rp[2], a2);
            a3 = fmaf(lk, rp[3], a3);
            a4 = fmaf(lk, rp[4], a4);
            a5 = fmaf(lk, rp[5], a5);
            a6 = fmaf(lk, rp[6], a6);
            a7 = fmaf(lk, rp[7], a7);
        }
        uint4 u;
        __half2 h;
        h = __floats2half2_rn(a0, a1); u.x = *reinterpret_cast<uint32_t*>(&h);
        h = __floats2half2_rn(a2, a3); u.y = *reinterpret_cast<uint32_t*>(&h);
        h = __floats2half2_rn(a4, a5); u.z = *reinterpret_cast<uint32_t*>(&h);
        h = __floats2half2_rn(a6, a7); u.w = *reinterpret_cast<uint32_t*>(&h);
        *reinterpret_cast<uint4*>(&g_w16[(size_t)o * 4096 + i0 + ii]) = u;
    }
}

// ============================================================
// GEMM  out[m][n] = sum_k x16[m][k]*w16[n][k] + bias[n]
// 256 threads, 8 warps (2 M x 4 N), warp tile 64x32, mma.m16n8k16
// 3-stage cp.async pipeline, 2 CTAs/SM, frag double-buffering,
// ROTATED pipeline: wait+sync sits in the ks=3 slot, next tile's
// ks=0 LDSMs interleave with the final MMAs (no exposed burst)
// ============================================================
__global__ __launch_bounds__(256, 2)
void gemm_kernel(const float* __restrict__ bias, float* __restrict__ out) {
    extern __shared__ char smem[];
    uint32_t sb = smem_u32(smem);
    int tid = threadIdx.x;
    int lane = tid & 31, wid = tid >> 5;
    int wm = wid >> 2;        // 0..1 (M)
    int wn = wid & 3;         // 0..3 (N)
    int mi = blockIdx.x >> 5, ni = blockIdx.x & 31;
    int m0 = mi * BM, n0 = ni * BN;

    // -------- cp.async tile copy: 128 rows x 64 halves (128B rows), swizzled --------
    int crow = tid >> 1;               // 0..127
    int ccb = (tid & 1) * 4;           // chunk base 0 or 4 (chunks of 8 halves = 16B)
    const __half* ga0 = g_x16 + (size_t)(m0 + crow) * KDIM + ccb * 8;
    const __half* gb0 = g_w16 + (size_t)(n0 + crow) * KDIM + ccb * 8;
    uint32_t arow = sb + crow * 128;

#define COPY_TILE(kt, st)                                                     \
    do {                                                                      \
        const __half* ga = ga0 + (kt) * BK;                                   \
        const __half* gb = gb0 + (kt) * BK;                                   \
        uint32_t ab = arow + (st) * STAGE_BYTES;                              \
        _Pragma("unroll")                                                     \
        for (int j = 0; j < 4; j++) {                                         \
            uint32_t so = (uint32_t)(((ccb + j) ^ (crow & 7)) * 16);          \
            cp16(ab + so, ga + j * 8);                                        \
            cp16(ab + B_OFF + so, gb + j * 8);                                \
        }                                                                     \
    } while (0)

    COPY_TILE(0, 0); cp_commit();
    COPY_TILE(1, 1); cp_commit();

    float acc[4][4][4];
#pragma unroll
    for (int a = 0; a < 4; a++)
#pragma unroll
        for (int b = 0; b < 4; b++)
#pragma unroll
            for (int c = 0; c < 4; c++) acc[a][b][c] = 0.0f;

    // ldmatrix per-lane row/chunk decomposition (precompute bases)
    int ra = lane & 15, ca = lane >> 4;                    // A: 16 rows x 2 k-chunks
    int rb = (lane & 7) + ((lane >> 4) << 3);              // B: 8+8 n-rows
    int cb2 = (lane >> 3) & 1;                             // B: k-chunk half
    uint32_t abase[4], bbase[2];
    int ax[4], bx[2];
#pragma unroll
    for (int mt = 0; mt < 4; mt++) {
        int row = wm * 64 + mt * 16 + ra;
        abase[mt] = (uint32_t)(row * 128);
        ax[mt] = row & 7;
    }
#pragma unroll
    for (int bt = 0; bt < 2; bt++) {
        int row = wn * 32 + bt * 16 + rb;
        bbase[bt] = (uint32_t)(B_OFF + row * 128);
        bx[bt] = row & 7;
    }

    // double-buffered fragments
    uint32_t af[2][4][4], bf[2][2][4];

#define LDA(st_, ks_, buf_, mt_)                                              \
    ldm_x4(af[buf_][mt_],                                                     \
           (st_) + abase[mt_] + (uint32_t)((((ks_)*2 + ca) ^ ax[mt_]) * 16))
#define LDB(st_, ks_, buf_, bt_)                                              \
    ldm_x4(bf[buf_][bt_],                                                     \
           (st_) + bbase[bt_] + (uint32_t)((((ks_)*2 + cb2) ^ bx[bt_]) * 16))

#define MMA_ROW(buf_, mt_)                                                    \
    do {                                                                      \
        _Pragma("unroll")                                                     \
        for (int nt = 0; nt < 4; nt++)                                        \
            mma16816(acc[mt_][nt], af[buf_][mt_],                             \
                     bf[buf_][nt >> 1][(nt & 1) * 2],                         \
                     bf[buf_][nt >> 1][(nt & 1) * 2 + 1]);                    \
    } while (0)

    // prologue: tile 0 ready, load its ks=0 fragments (one exposed burst total)
    cp_wait1();
    __syncthreads();
    LDA(sb, 0, 0, 0); LDB(sb, 0, 0, 0); LDB(sb, 0, 0, 1);
    LDA(sb, 0, 0, 1); LDA(sb, 0, 0, 2); LDA(sb, 0, 0, 3);

    int cs = 0, ps = 2;   // compute stage / prefetch stage (mod 3)
    for (int kt = 0; kt < NKT; kt++) {
        uint32_t st = sb + cs * STAGE_BYTES;
        bool docopy = (kt + 2 < NKT);
        const __half* pa = ga0 + (kt + 2) * BK;
        const __half* pb = gb0 + (kt + 2) * BK;
        uint32_t ab = arow + (uint32_t)(ps * STAGE_BYTES);
#pragma unroll
        for (int ks = 0; ks < 3; ks++) {
            int cur = ks & 1, nxt = cur ^ 1;
            if (docopy) {   // 2 cp16 per ks: smooth LSU/port usage
                uint32_t so = (uint32_t)(((ccb + ks) ^ (crow & 7)) * 16);
                cp16(ab + so, pa + ks * 8);
                cp16(ab + B_OFF + so, pb + ks * 8);
            }
            // interleave next-ks LDSMs between MMA rows (spread read bursts)
            LDB(st, ks + 1, nxt, 0); LDB(st, ks + 1, nxt, 1);
            MMA_ROW(cur, 0);
            LDA(st, ks + 1, nxt, 0); LDA(st, ks + 1, nxt, 1);
            MMA_ROW(cur, 1);
            LDA(st, ks + 1, nxt, 2);
            MMA_ROW(cur, 2);
            LDA(st, ks + 1, nxt, 3);
            MMA_ROW(cur, 3);
        }
        // ks == 3 (fragments in buf 1): finish copies, advance pipeline,
        // and interleave NEXT tile's ks=0 loads with the final MMAs
        if (docopy) {
            uint32_t so = (uint32_t)(((ccb + 3) ^ (crow & 7)) * 16);
            cp16(ab + so, pa + 24);
            cp16(ab + B_OFF + so, pb + 24);
        }
        cp_commit();
        if (kt + 1 < NKT) {
            cp_wait1();          // next tile's stage is ready
            __syncthreads();     // all warps done reading current stage
            uint32_t st2 = sb + ((cs == 2) ? 0 : cs + 1) * STAGE_BYTES;
            LDB(st2, 0, 0, 0); LDB(st2, 0, 0, 1);
            MMA_ROW(1, 0);
            LDA(st2, 0, 0, 0); LDA(st2, 0, 0, 1);
            MMA_ROW(1, 1);
            LDA(st2, 0, 0, 2);
            MMA_ROW(1, 2);
            LDA(st2, 0, 0, 3);
            MMA_ROW(1, 3);
        } else {
            MMA_ROW(1, 0); MMA_ROW(1, 1); MMA_ROW(1, 2); MMA_ROW(1, 3);
        }
        cs = (cs == 2) ? 0 : cs + 1;
        ps = (ps == 2) ? 0 : ps + 1;
    }

    // -------- epilogue: direct float2 stores + bias --------
    int r4 = lane >> 2, c2 = (lane & 3) * 2;
#pragma unroll
    for (int nt = 0; nt < 4; nt++) {
        int n = n0 + wn * 32 + nt * 8 + c2;
        float2 bv = *reinterpret_cast<const float2*>(&bias[n]);
#pragma unroll
        for (int mt = 0; mt < 4; mt++) {
            int m = m0 + wm * 64 + mt * 16 + r4;
            float2 v0 = {acc[mt][nt][0] + bv.x, acc[mt][nt][1] + bv.y};
            float2 v1 = {acc[mt][nt][2] + bv.x, acc[mt][nt][3] + bv.y};
            *reinterpret_cast<float2*>(&out[(size_t)m * NDIM + n]) = v0;
            *reinterpret_cast<float2*>(&out[(size_t)(m + 8) * NDIM + n]) = v1;
        }
    }
}

// ============================================================
// launcher
// ============================================================
extern "C" void kernel_launch(void* const* d_in, const int* in_sizes, int n_in,
                              void* d_out, int out_size) {
    const float* x = (const float*)d_in[0];
    const float* W = (const float*)d_in[1];
    const float* bias = (const float*)d_in[2];
    const float* L = (const float*)d_in[3];
    const float* R = (const float*)d_in[4];
    float* out = (float*)d_out;

    cudaFuncSetAttribute(gemm_kernel, cudaFuncAttributeMaxDynamicSharedMemorySize, SMEM_TOTAL);

    cvt_kernel<<<(MDIM * KDIM) / 8 / 256, 256>>>(x);
    weff_kernel<<<2048, 256>>>(W, L, R);
    gemm_kernel<<<GRID_GEMM, 256, SMEM_TOTAL>>>(bias, out);
}

// round 16
// speedup vs baseline: 1.1128x; 1.1128x over previous
#include <cuda_runtime.h>
#include <cuda_fp16.h>
#include <cstdint>

#define DI __device__ __forceinline__

// ---------------- problem dims ----------------
#define MDIM 8192
#define NDIM 4096
#define KDIM 4096
#define BM 128
#define BN 128
#define BK 64
#define STAGES 3
#define NKT (KDIM / BK)            // 64
#define STAGE_BYTES 32768          // A 16KB + B 16KB
#define B_OFF 16384
#define SMEM_TOTAL (STAGES * STAGE_BYTES)   // 96 KB -> 2 CTAs/SM
#define GRID_GEMM ((MDIM / BM) * (NDIM / BN))  // 2048

// scratch (allocation-free rule: __device__ globals)
__device__ __half g_x16[(size_t)MDIM * KDIM];   // 67 MB
__device__ __half g_w16[(size_t)NDIM * KDIM];   // 33.5 MB

// ---------------- PTX helpers (baseline sm_80+ features only) ----------------
DI uint32_t smem_u32(const void* p) {
    uint32_t a;
    asm("{ .reg .u64 t; cvta.to.shared.u64 t, %1; cvt.u32.u64 %0, t; }" : "=r"(a) : "l"(p));
    return a;
}
DI void cp16(uint32_t dst, const void* src) {
    asm volatile("cp.async.cg.shared.global [%0], [%1], 16;" :: "r"(dst), "l"(src) : "memory");
}
DI void cp_commit() { asm volatile("cp.async.commit_group;" ::: "memory"); }
DI void cp_wait1() { asm volatile("cp.async.wait_group 1;" ::: "memory"); }

DI void ldm_x4(uint32_t* r, uint32_t addr) {
    asm volatile("ldmatrix.sync.aligned.m8n8.x4.shared.b16 {%0,%1,%2,%3}, [%4];"
                 : "=r"(r[0]), "=r"(r[1]), "=r"(r[2]), "=r"(r[3]) : "r"(addr));
}
DI void mma16816(float* c, const uint32_t* a, uint32_t b0, uint32_t b1) {
    asm volatile(
        "mma.sync.aligned.m16n8k16.row.col.f32.f16.f16.f32 "
        "{%0,%1,%2,%3}, {%4,%5,%6,%7}, {%8,%9}, {%0,%1,%2,%3};"
        : "+f"(c[0]), "+f"(c[1]), "+f"(c[2]), "+f"(c[3])
        : "r"(a[0]), "r"(a[1]), "r"(a[2]), "r"(a[3]), "r"(b0), "r"(b1));
}

// ============================================================
// Kernel 1: x fp32 -> fp16 (RNE), 16-byte stores
// ============================================================
__global__ void cvt_kernel(const float* __restrict__ x) {
    size_t i = (size_t)(blockIdx.x * blockDim.x + threadIdx.x) * 2;  // 2 float4 per thread
    float4 v0 = reinterpret_cast<const float4*>(x)[i];
    float4 v1 = reinterpret_cast<const float4*>(x)[i + 1];
    uint4 u;
    __half2 h;
    h = __floats2half2_rn(v0.x, v0.y); u.x = *reinterpret_cast<uint32_t*>(&h);
    h = __floats2half2_rn(v0.z, v0.w); u.y = *reinterpret_cast<uint32_t*>(&h);
    h = __floats2half2_rn(v1.x, v1.y); u.z = *reinterpret_cast<uint32_t*>(&h);
    h = __floats2half2_rn(v1.z, v1.w); u.w = *reinterpret_cast<uint32_t*>(&h);
    reinterpret_cast<uint4*>(g_x16)[i / 2] = u;
}

// ============================================================
// Kernel 2: w16 = fp16(W + 2 * L @ R)   (LORA_SCALE = 32/16 = 2)
// 2048 blocks: (16 o-rows) x (512-col i-chunk); 16-byte stores
// threads: 64 i-groups (8 cols each) x 4 oo-groups (4 rows each)
// ============================================================
__global__ __launch_bounds__(256)
void weff_kernel(const float* __restrict__ W, const float* __restrict__ L,
                 const float* __restrict__ R) {
    __shared__ float Rs[16][512];
    __shared__ float Ls[16][16];
    int o0 = (blockIdx.x >> 3) * 16;          // 256 o-groups
    int i0 = (blockIdx.x & 7) * 512;          // 8 i-chunks
    int tid = threadIdx.x;
    {
        int oo = tid >> 4, k = tid & 15;
        Ls[oo][k] = 2.0f * L[(o0 + oo) * 16 + k];
    }
#pragma unroll
    for (int j = 0; j < 8; j++) {
        int idx = tid + j * 256;              // float4 index into 16x512 tile
        int k = idx >> 7;
        int ii = (idx & 127) << 2;
        *reinterpret_cast<float4*>(&Rs[k][ii]) =
            *reinterpret_cast<const float4*>(&R[(size_t)k * 4096 + i0 + ii]);
    }
    __syncthreads();
    int ii = (tid & 63) * 8;                  // 8 consecutive i per thread
    int og = (tid >> 6) * 4;                  // 4 rows per thread
#pragma unroll
    for (int oo4 = 0; oo4 < 4; oo4++) {
        int o = o0 + og + oo4;
        const float* wp = &W[(size_t)o * 4096 + i0 + ii];
        float4 w0 = *reinterpret_cast<const float4*>(wp);
        float4 w1 = *reinterpret_cast<const float4*>(wp + 4);
        float a0 = w0.x, a1 = w0.y, a2 = w0.z, a3 = w0.w;
        float a4 = w1.x, a5 = w1.y, a6 = w1.z, a7 = w1.w;
#pragma unroll
        for (int k = 0; k < 16; k++) {
            float lk = Ls[og + oo4][k];
            const float* rp = &Rs[k][ii];
            a0 = fmaf(lk, rp[0], a0);
            a1 = fmaf(lk, rp[1], a1);
            a2 = fmaf(lk, rp[2], a2);
            a3 = fmaf(lk, rp[3], a3);
            a4 = fmaf(lk, rp[4], a4);
            a5 = fmaf(lk, rp[5], a5);
            a6 = fmaf(lk, rp[6], a6);
            a7 = fmaf(lk, rp[7], a7);
        }
        uint4 u;
        __half2 h;
        h = __floats2half2_rn(a0, a1); u.x = *reinterpret_cast<uint32_t*>(&h);
        h = __floats2half2_rn(a2, a3); u.y = *reinterpret_cast<uint32_t*>(&h);
        h = __floats2half2_rn(a4, a5); u.z = *reinterpret_cast<uint32_t*>(&h);
        h = __floats2half2_rn(a6, a7); u.w = *reinterpret_cast<uint32_t*>(&h);
        *reinterpret_cast<uint4*>(&g_w16[(size_t)o * 4096 + i0 + ii]) = u;
    }
}

// ============================================================
// GEMM  out[m][n] = sum_k x16[m][k]*w16[n][k] + bias[n]
// 256 threads, 8 warps (2 M x 4 N), warp tile 64x32, mma.m16n8k16
// 3-stage cp.async pipeline, 2 CTAs/SM, frag double-buffering,
// cp.async AND ldmatrix spread across/through the MMA stream
// (REVERTED to R14 exactly — R15 rotation regressed; barrier placement
//  at top-of-loop is load-bearing)
// ============================================================
__global__ __launch_bounds__(256, 2)
void gemm_kernel(const float* __restrict__ bias, float* __restrict__ out) {
    extern __shared__ char smem[];
    uint32_t sb = smem_u32(smem);
    int tid = threadIdx.x;
    int lane = tid & 31, wid = tid >> 5;
    int wm = wid >> 2;        // 0..1 (M)
    int wn = wid & 3;         // 0..3 (N)
    int mi = blockIdx.x >> 5, ni = blockIdx.x & 31;
    int m0 = mi * BM, n0 = ni * BN;

    // -------- cp.async tile copy: 128 rows x 64 halves (128B rows), swizzled --------
    int crow = tid >> 1;               // 0..127
    int ccb = (tid & 1) * 4;           // chunk base 0 or 4 (chunks of 8 halves = 16B)
    const __half* ga0 = g_x16 + (size_t)(m0 + crow) * KDIM + ccb * 8;
    const __half* gb0 = g_w16 + (size_t)(n0 + crow) * KDIM + ccb * 8;
    uint32_t arow = sb + crow * 128;

#define COPY_TILE(kt, st)                                                     \
    do {                                                                      \
        const __half* ga = ga0 + (kt) * BK;                                   \
        const __half* gb = gb0 + (kt) * BK;                                   \
        uint32_t ab = arow + (st) * STAGE_BYTES;                              \
        _Pragma("unroll")                                                     \
        for (int j = 0; j < 4; j++) {                                         \
            uint32_t so = (uint32_t)(((ccb + j) ^ (crow & 7)) * 16);          \
            cp16(ab + so, ga + j * 8);                                        \
            cp16(ab + B_OFF + so, gb + j * 8);                                \
        }                                                                     \
    } while (0)

    COPY_TILE(0, 0); cp_commit();
    COPY_TILE(1, 1); cp_commit();

    float acc[4][4][4];
#pragma unroll
    for (int a = 0; a < 4; a++)
#pragma unroll
        for (int b = 0; b < 4; b++)
#pragma unroll
            for (int c = 0; c < 4; c++) acc[a][b][c] = 0.0f;

    // ldmatrix per-lane row/chunk decomposition (precompute bases)
    int ra = lane & 15, ca = lane >> 4;                    // A: 16 rows x 2 k-chunks
    int rb = (lane & 7) + ((lane >> 4) << 3);              // B: 8+8 n-rows
    int cb2 = (lane >> 3) & 1;                             // B: k-chunk half
    uint32_t abase[4], bbase[2];
    int ax[4], bx[2];
#pragma unroll
    for (int mt = 0; mt < 4; mt++) {
        int row = wm * 64 + mt * 16 + ra;
        abase[mt] = (uint32_t)(row * 128);
        ax[mt] = row & 7;
    }
#pragma unroll
    for (int bt = 0; bt < 2; bt++) {
        int row = wn * 32 + bt * 16 + rb;
        bbase[bt] = (uint32_t)(B_OFF + row * 128);
        bx[bt] = row & 7;
    }

    // double-buffered fragments
    uint32_t af[2][4][4], bf[2][2][4];

#define LDA(ks_, buf_, mt_)                                                   \
    ldm_x4(af[buf_][mt_],                                                     \
           st + abase[mt_] + (uint32_t)((((ks_)*2 + ca) ^ ax[mt_]) * 16))
#define LDB(ks_, buf_, bt_)                                                   \
    ldm_x4(bf[buf_][bt_],                                                     \
           st + bbase[bt_] + (uint32_t)((((ks_)*2 + cb2) ^ bx[bt_]) * 16))

#define MMA_ROW(buf_, mt_)                                                    \
    do {                                                                      \
        _Pragma("unroll")                                                     \
        for (int nt = 0; nt < 4; nt++)                                        \
            mma16816(acc[mt_][nt], af[buf_][mt_],                             \
                     bf[buf_][nt >> 1][(nt & 1) * 2],                         \
                     bf[buf_][nt >> 1][(nt & 1) * 2 + 1]);                    \
    } while (0)

    int cs = 0, ps = 2;   // compute stage / prefetch stage (mod 3)
    for (int kt = 0; kt < NKT; kt++) {
        cp_wait1();
        __syncthreads();
        uint32_t st = sb + cs * STAGE_BYTES;
        // ks=0 fragments, dependency-first: MMA_ROW(0) needs af[0][0]+bf[0][*]
        LDA(0, 0, 0); LDB(0, 0, 0); LDB(0, 0, 1);
        LDA(0, 0, 1); LDA(0, 0, 2); LDA(0, 0, 3);
        // prefetch-tile pointers for kt+2 (cp.async spread across ks loop)
        bool docopy = (kt + 2 < NKT);
        const __half* pa = ga0 + (kt + 2) * BK;
        const __half* pb = gb0 + (kt + 2) * BK;
        uint32_t ab = arow + (uint32_t)(ps * STAGE_BYTES);
#pragma unroll
        for (int ks = 0; ks < 4; ks++) {
            int cur = ks & 1, nxt = cur ^ 1;
            if (docopy) {   // 2 cp16 per ks: smooth LSU/port usage
                uint32_t so = (uint32_t)(((ccb + ks) ^ (crow & 7)) * 16);
                cp16(ab + so, pa + ks * 8);
                cp16(ab + B_OFF + so, pb + ks * 8);
            }
            // interleave next-ks LDSMs between MMA rows (spread read bursts)
            if (ks < 3) {
                LDB(ks + 1, nxt, 0); LDB(ks + 1, nxt, 1);
                MMA_ROW(cur, 0);
                LDA(ks + 1, nxt, 0); LDA(ks + 1, nxt, 1);
                MMA_ROW(cur, 1);
                LDA(ks + 1, nxt, 2);
                MMA_ROW(cur, 2);
                LDA(ks + 1, nxt, 3);
                MMA_ROW(cur, 3);
            } else {
                MMA_ROW(cur, 0); MMA_ROW(cur, 1); MMA_ROW(cur, 2); MMA_ROW(cur, 3);
            }
        }
        cp_commit();
        cs = (cs == 2) ? 0 : cs + 1;
        ps = (ps == 2) ? 0 : ps + 1;
    }

    // -------- epilogue: direct float2 stores + bias --------
    int r4 = lane >> 2, c2 = (lane & 3) * 2;
#pragma unroll
    for (int nt = 0; nt < 4; nt++) {
        int n = n0 + wn * 32 + nt * 8 + c2;
        float2 bv = *reinterpret_cast<const float2*>(&bias[n]);
#pragma unroll
        for (int mt = 0; mt < 4; mt++) {
            int m = m0 + wm * 64 + mt * 16 + r4;
            float2 v0 = {acc[mt][nt][0] + bv.x, acc[mt][nt][1] + bv.y};
            float2 v1 = {acc[mt][nt][2] + bv.x, acc[mt][nt][3] + bv.y};
            *reinterpret_cast<float2*>(&out[(size_t)m * NDIM + n]) = v0;
            *reinterpret_cast<float2*>(&out[(size_t)(m + 8) * NDIM + n]) = v1;
        }
    }
}

// ============================================================
// launcher
// ============================================================
extern "C" void kernel_launch(void* const* d_in, const int* in_sizes, int n_in,
                              void* d_out, int out_size) {
    const float* x = (const float*)d_in[0];
    const float* W = (const float*)d_in[1];
    const float* bias = (const float*)d_in[2];
    const float* L = (const float*)d_in[3];
    const float* R = (const float*)d_in[4];
    float* out = (float*)d_out;

    cudaFuncSetAttribute(gemm_kernel, cudaFuncAttributeMaxDynamicSharedMemorySize, SMEM_TOTAL);

    cvt_kernel<<<(MDIM * KDIM) / 8 / 256, 256>>>(x);
    weff_kernel<<<2048, 256>>>(W, L, R);
    gemm_kernel<<<GRID_GEMM, 256, SMEM_TOTAL>>>(bias, out);
}

// round 17
// speedup vs baseline: 1.1359x; 1.0208x over previous
#include <cuda_runtime.h>
#include <cuda_fp16.h>
#include <cstdint>

#define DI __device__ __forceinline__

// ---------------- problem dims ----------------
#define MDIM 8192
#define NDIM 4096
#define KDIM 4096
#define BM 128
#define BN 128
#define BK 64
#define STAGES 3
#define NKT (KDIM / BK)            // 64
#define STAGE_BYTES 32768          // A 16KB + B 16KB
#define B_OFF 16384
#define SMEM_TOTAL (STAGES * STAGE_BYTES)   // 96 KB -> 2 CTAs/SM
#define GRID_GEMM ((MDIM / BM) * (NDIM / BN))  // 2048

// scratch (allocation-free rule: __device__ globals)
__device__ __half g_x16[(size_t)MDIM * KDIM];   // 67 MB
__device__ __half g_w16[(size_t)NDIM * KDIM];   // 33.5 MB

// ---------------- PTX helpers (baseline sm_80+ features only) ----------------
DI uint32_t smem_u32(const void* p) {
    uint32_t a;
    asm("{ .reg .u64 t; cvta.to.shared.u64 t, %1; cvt.u32.u64 %0, t; }" : "=r"(a) : "l"(p));
    return a;
}
DI void cp16(uint32_t dst, const void* src) {
    asm volatile("cp.async.cg.shared.global [%0], [%1], 16;" :: "r"(dst), "l"(src) : "memory");
}
DI void cp_commit() { asm volatile("cp.async.commit_group;" ::: "memory"); }
DI void cp_wait1() { asm volatile("cp.async.wait_group 1;" ::: "memory"); }

DI void ldm_x4(uint32_t* r, uint32_t addr) {
    asm volatile("ldmatrix.sync.aligned.m8n8.x4.shared.b16 {%0,%1,%2,%3}, [%4];"
                 : "=r"(r[0]), "=r"(r[1]), "=r"(r[2]), "=r"(r[3]) : "r"(addr));
}
DI void mma16816(float* c, const uint32_t* a, uint32_t b0, uint32_t b1) {
    asm volatile(
        "mma.sync.aligned.m16n8k16.row.col.f32.f16.f16.f32 "
        "{%0,%1,%2,%3}, {%4,%5,%6,%7}, {%8,%9}, {%0,%1,%2,%3};"
        : "+f"(c[0]), "+f"(c[1]), "+f"(c[2]), "+f"(c[3])
        : "r"(a[0]), "r"(a[1]), "r"(a[2]), "r"(a[3]), "r"(b0), "r"(b1));
}

// ============================================================
// Kernel 1: x fp32 -> fp16 (RNE), streaming loads, 16-byte stores
// ============================================================
__global__ void cvt_kernel(const float* __restrict__ x) {
    size_t i = (size_t)(blockIdx.x * blockDim.x + threadIdx.x) * 2;  // 2 float4 per thread
    float4 v0 = __ldcs(reinterpret_cast<const float4*>(x) + i);
    float4 v1 = __ldcs(reinterpret_cast<const float4*>(x) + i + 1);
    uint4 u;
    __half2 h;
    h = __floats2half2_rn(v0.x, v0.y); u.x = *reinterpret_cast<uint32_t*>(&h);
    h = __floats2half2_rn(v0.z, v0.w); u.y = *reinterpret_cast<uint32_t*>(&h);
    h = __floats2half2_rn(v1.x, v1.y); u.z = *reinterpret_cast<uint32_t*>(&h);
    h = __floats2half2_rn(v1.z, v1.w); u.w = *reinterpret_cast<uint32_t*>(&h);
    reinterpret_cast<uint4*>(g_x16)[i / 2] = u;
}

// ============================================================
// Kernel 2: w16 = fp16(W + 2 * L @ R)   (LORA_SCALE = 32/16 = 2)
// 2048 blocks: (16 o-rows) x (512-col i-chunk); 16-byte stores,
// streaming W loads (read-once)
// ============================================================
__global__ __launch_bounds__(256)
void weff_kernel(const float* __restrict__ W, const float* __restrict__ L,
                 const float* __restrict__ R) {
    __shared__ float Rs[16][512];
    __shared__ float Ls[16][16];
    int o0 = (blockIdx.x >> 3) * 16;          // 256 o-groups
    int i0 = (blockIdx.x & 7) * 512;          // 8 i-chunks
    int tid = threadIdx.x;
    {
        int oo = tid >> 4, k = tid & 15;
        Ls[oo][k] = 2.0f * L[(o0 + oo) * 16 + k];
    }
#pragma unroll
    for (int j = 0; j < 8; j++) {
        int idx = tid + j * 256;              // float4 index into 16x512 tile
        int k = idx >> 7;
        int ii = (idx & 127) << 2;
        *reinterpret_cast<float4*>(&Rs[k][ii]) =
            *reinterpret_cast<const float4*>(&R[(size_t)k * 4096 + i0 + ii]);
    }
    __syncthreads();
    int ii = (tid & 63) * 8;                  // 8 consecutive i per thread
    int og = (tid >> 6) * 4;                  // 4 rows per thread
#pragma unroll
    for (int oo4 = 0; oo4 < 4; oo4++) {
        int o = o0 + og + oo4;
        const float4* wp = reinterpret_cast<const float4*>(&W[(size_t)o * 4096 + i0 + ii]);
        float4 w0 = __ldcs(wp);
        float4 w1 = __ldcs(wp + 1);
        float a0 = w0.x, a1 = w0.y, a2 = w0.z, a3 = w0.w;
        float a4 = w1.x, a5 = w1.y, a6 = w1.z, a7 = w1.w;
#pragma unroll
        for (int k = 0; k < 16; k++) {
            float lk = Ls[og + oo4][k];
            const float* rp = &Rs[k][ii];
            a0 = fmaf(lk, rp[0], a0);
            a1 = fmaf(lk, rp[1], a1);
            a2 = fmaf(lk, rp[2], a2);
            a3 = fmaf(lk, rp[3], a3);
            a4 = fmaf(lk, rp[4], a4);
            a5 = fmaf(lk, rp[5], a5);
            a6 = fmaf(lk, rp[6], a6);
            a7 = fmaf(lk, rp[7], a7);
        }
        uint4 u;
        __half2 h;
        h = __floats2half2_rn(a0, a1); u.x = *reinterpret_cast<uint32_t*>(&h);
        h = __floats2half2_rn(a2, a3); u.y = *reinterpret_cast<uint32_t*>(&h);
        h = __floats2half2_rn(a4, a5); u.z = *reinterpret_cast<uint32_t*>(&h);
        h = __floats2half2_rn(a6, a7); u.w = *reinterpret_cast<uint32_t*>(&h);
        *reinterpret_cast<uint4*>(&g_w16[(size_t)o * 4096 + i0 + ii]) = u;
    }
}

// ============================================================
// GEMM  out[m][n] = sum_k x16[m][k]*w16[n][k] + bias[n]
// 256 threads, 8 warps (2 M x 4 N), warp tile 64x32, mma.m16n8k16
// 3-stage cp.async pipeline, 2 CTAs/SM, frag double-buffering,
// cp.async + ldmatrix spread through the MMA stream (R14 structure),
// kt-loop unrolled x3 so stage offsets are compile-time constants
// ============================================================
__global__ __launch_bounds__(256, 2)
void gemm_kernel(const float* __restrict__ bias, float* __restrict__ out) {
    extern __shared__ char smem[];
    uint32_t sb = smem_u32(smem);
    int tid = threadIdx.x;
    int lane = tid & 31, wid = tid >> 5;
    int wm = wid >> 2;        // 0..1 (M)
    int wn = wid & 3;         // 0..3 (N)
    int mi = blockIdx.x >> 5, ni = blockIdx.x & 31;
    int m0 = mi * BM, n0 = ni * BN;

    // -------- cp.async tile copy: 128 rows x 64 halves (128B rows), swizzled --------
    int crow = tid >> 1;               // 0..127
    int ccb = (tid & 1) * 4;           // chunk base 0 or 4 (chunks of 8 halves = 16B)
    const __half* ga0 = g_x16 + (size_t)(m0 + crow) * KDIM + ccb * 8;
    const __half* gb0 = g_w16 + (size_t)(n0 + crow) * KDIM + ccb * 8;
    uint32_t arow = sb + crow * 128;

#define COPY_TILE(kt, st)                                                     \
    do {                                                                      \
        const __half* ga = ga0 + (kt) * BK;                                   \
        const __half* gb = gb0 + (kt) * BK;                                   \
        uint32_t ab = arow + (st) * STAGE_BYTES;                              \
        _Pragma("unroll")                                                     \
        for (int j = 0; j < 4; j++) {                                         \
            uint32_t so = (uint32_t)(((ccb + j) ^ (crow & 7)) * 16);          \
            cp16(ab + so, ga + j * 8);                                        \
            cp16(ab + B_OFF + so, gb + j * 8);                                \
        }                                                                     \
    } while (0)

    COPY_TILE(0, 0); cp_commit();
    COPY_TILE(1, 1); cp_commit();

    float acc[4][4][4];
#pragma unroll
    for (int a = 0; a < 4; a++)
#pragma unroll
        for (int b = 0; b < 4; b++)
#pragma unroll
            for (int c = 0; c < 4; c++) acc[a][b][c] = 0.0f;

    // ldmatrix per-lane row/chunk decomposition (precompute bases)
    int ra = lane & 15, ca = lane >> 4;                    // A: 16 rows x 2 k-chunks
    int rb = (lane & 7) + ((lane >> 4) << 3);              // B: 8+8 n-rows
    int cb2 = (lane >> 3) & 1;                             // B: k-chunk half
    uint32_t abase[4], bbase[2];
    int ax[4], bx[2];
#pragma unroll
    for (int mt = 0; mt < 4; mt++) {
        int row = wm * 64 + mt * 16 + ra;
        abase[mt] = (uint32_t)(row * 128);
        ax[mt] = row & 7;
    }
#pragma unroll
    for (int bt = 0; bt < 2; bt++) {
        int row = wn * 32 + bt * 16 + rb;
        bbase[bt] = (uint32_t)(B_OFF + row * 128);
        bx[bt] = row & 7;
    }

    // double-buffered fragments
    uint32_t af[2][4][4], bf[2][2][4];

#define LDA(st_, ks_, buf_, mt_)                                              \
    ldm_x4(af[buf_][mt_],                                                     \
           (st_) + abase[mt_] + (uint32_t)((((ks_)*2 + ca) ^ ax[mt_]) * 16))
#define LDB(st_, ks_, buf_, bt_)                                              \
    ldm_x4(bf[buf_][bt_],                                                     \
           (st_) + bbase[bt_] + (uint32_t)((((ks_)*2 + cb2) ^ bx[bt_]) * 16))

#define MMA_ROW(buf_, mt_)                                                    \
    do {                                                                      \
        _Pragma("unroll")                                                     \
        for (int nt = 0; nt < 4; nt++)                                        \
            mma16816(acc[mt_][nt], af[buf_][mt_],                             \
                     bf[buf_][nt >> 1][(nt & 1) * 2],                         \
                     bf[buf_][nt >> 1][(nt & 1) * 2 + 1]);                    \
    } while (0)

    // one kt iteration with COMPILE-TIME stage indices CS_ (compute) / PS_ (prefetch)
#define GEMM_BODY(CS_, PS_)                                                   \
    do {                                                                      \
        cp_wait1();                                                           \
        __syncthreads();                                                      \
        const uint32_t st = sb + (CS_) * STAGE_BYTES;                         \
        LDA(st, 0, 0, 0); LDB(st, 0, 0, 0); LDB(st, 0, 0, 1);                 \
        LDA(st, 0, 0, 1); LDA(st, 0, 0, 2); LDA(st, 0, 0, 3);                 \
        bool docopy = (kt + 2 < NKT);                                         \
        const __half* pa = ga0 + (kt + 2) * BK;                               \
        const __half* pb = gb0 + (kt + 2) * BK;                               \
        uint32_t ab = arow + (uint32_t)((PS_) * STAGE_BYTES);                 \
        _Pragma("unroll")                                                     \
        for (int ks = 0; ks < 4; ks++) {                                      \
            int cur = ks & 1, nxt = cur ^ 1;                                  \
            if (docopy) {                                                     \
                uint32_t so = (uint32_t)(((ccb + ks) ^ (crow & 7)) * 16);     \
                cp16(ab + so, pa + ks * 8);                                   \
                cp16(ab + B_OFF + so, pb + ks * 8);                           \
            }                                                                 \
            if (ks < 3) {                                                     \
                LDB(st, ks + 1, nxt, 0); LDB(st, ks + 1, nxt, 1);             \
                MMA_ROW(cur, 0);                                              \
                LDA(st, ks + 1, nxt, 0); LDA(st, ks + 1, nxt, 1);             \
                MMA_ROW(cur, 1);                                              \
                LDA(st, ks + 1, nxt, 2);                                      \
                MMA_ROW(cur, 2);                                              \
                LDA(st, ks + 1, nxt, 3);                                      \
                MMA_ROW(cur, 3);                                              \
            } else {                                                          \
                MMA_ROW(cur, 0); MMA_ROW(cur, 1);                             \
                MMA_ROW(cur, 2); MMA_ROW(cur, 3);                             \
            }                                                                 \
        }                                                                     \
        cp_commit();                                                          \
        kt++;                                                                 \
    } while (0)

    int kt = 0;
#pragma unroll 1
    for (int k3 = 0; k3 < 21; k3++) {   // 63 tiles: stage pattern (0,2),(1,0),(2,1)
        GEMM_BODY(0, 2);
        GEMM_BODY(1, 0);
        GEMM_BODY(2, 1);
    }
    GEMM_BODY(0, 2);                    // kt = 63: cs=0, ps=2 (matches 63 mod 3)

    // -------- epilogue: direct float2 stores + bias --------
    int r4 = lane >> 2, c2 = (lane & 3) * 2;
#pragma unroll
    for (int nt = 0; nt < 4; nt++) {
        int n = n0 + wn * 32 + nt * 8 + c2;
        float2 bv = *reinterpret_cast<const float2*>(&bias[n]);
#pragma unroll
        for (int mt = 0; mt < 4; mt++) {
            int m = m0 + wm * 64 + mt * 16 + r4;
            float2 v0 = {acc[mt][nt][0] + bv.x, acc[mt][nt][1] + bv.y};
            float2 v1 = {acc[mt][nt][2] + bv.x, acc[mt][nt][3] + bv.y};
            *reinterpret_cast<float2*>(&out[(size_t)m * NDIM + n]) = v0;
            *reinterpret_cast<float2*>(&out[(size_t)(m + 8) * NDIM + n]) = v1;
        }
    }
}

// ============================================================
// launcher
// ============================================================
extern "C" void kernel_launch(void* const* d_in, const int* in_sizes, int n_in,
                              void* d_out, int out_size) {
    const float* x = (const float*)d_in[0];
    const float* W = (const float*)d_in[1];
    const float* bias = (const float*)d_in[2];
    const float* L = (const float*)d_in[3];
    const float* R = (const float*)d_in[4];
    float* out = (float*)d_out;

    cudaFuncSetAttribute(gemm_kernel, cudaFuncAttributeMaxDynamicSharedMemorySize, SMEM_TOTAL);

    cvt_kernel<<<(MDIM * KDIM) / 8 / 256, 256>>>(x);
    weff_kernel<<<2048, 256>>>(W, L, R);
    gemm_kernel<<<GRID_GEMM, 256, SMEM_TOTAL>>>(bias, out);
}